// round 14
// baseline (speedup 1.0000x reference)
#include <cuda_runtime.h>
#include <cuda_bf16.h>
#include <cstdint>

// Problem constants (from reference)
#define S_GRID 7
#define B_BOX 2
#define C_CLS 20
#define CH (B_BOX * 5 + C_CLS)            // 30 channels
#define CELLS (S_GRID * S_GRID)           // 49
#define IMG_FLOATS (CELLS * CH)           // 1470
#define N_IMG 16384
#define T_TGT 32
#define LAMBDA_COORD 5.0f
#define LAMBDA_NOOBJ 0.5f

#define THREADS 256
// A-blocks: pure coalesced stream computing global sum(conf^2)
#define A_BLOCKS 780                      // 780*256 = 199680, % 15 == 0
#define A_STRIDE (A_BLOCKS * THREADS)
#define NV4 (N_IMG * IMG_FLOATS / 4)      // 6,021,120 float4 (exact)
// B-blocks: per-target math, warp-per-image, 4 images per warp
#define B_BLOCKS 512
#define B_WARPS (B_BLOCKS * (THREADS / 32))   // 4096
#define IMGS_PER_WARP (N_IMG / B_WARPS)       // 4
#define GRID_T (A_BLOCKS + B_BLOCKS)          // 1292

__device__ float g_partial[GRID_T];
__device__ unsigned int g_count;          // zero-init; returns to 0 every launch

__global__ void __launch_bounds__(THREADS)
yolo_split_kernel(const float* __restrict__ outputs,
                  const float* __restrict__ tboxes,
                  const int*   __restrict__ tlabels,
                  float*       __restrict__ out)
{
    __shared__ float swsum[THREADS / 32];
    __shared__ int s_is_last;
    __shared__ double sd[THREADS];

    const int tid = threadIdx.x;
    const int wid = tid >> 5;
    const int lid = tid & 31;

    float lane_acc = 0.0f;

    if (blockIdx.x < A_BLOCKS) {
        // ================== A: coalesced conf^2 stream ==================
        // float4 index j: j%15==2 -> (x,y) are conf ch8,9; j%15==9 -> (z,w).
        // A_STRIDE % 15 == 0 keeps each thread's residue constant.
        const int gtid = blockIdx.x * THREADS + tid;
        const float4* __restrict__ o4 = reinterpret_cast<const float4*>(outputs);
        const int r = gtid % 15;
        const bool p2 = (r == 2);
        const bool p9 = (r == 9);
        float confsq = 0.0f;
        #pragma unroll 6
        for (int i = gtid; i < NV4; i += A_STRIDE) {
            const float4 v = o4[i];
            if (p2) confsq += v.x * v.x + v.y * v.y;
            if (p9) confsq += v.z * v.z + v.w * v.w;
        }
        lane_acc = (LAMBDA_NOOBJ / 98.0f) * confsq;
    } else {
        // ================== B: per-target math (R13 core) ==================
        const int bwarp = (blockIdx.x - A_BLOCKS) * (THREADS / 32) + wid;
        const float cell = 1.0f / (float)S_GRID;

        #pragma unroll
        for (int k = 0; k < IMGS_PER_WARP; k++) {
            const int n = bwarp + k * B_WARPS;

            const float4 tb = *reinterpret_cast<const float4*>(
                tboxes + ((size_t)n * T_TGT + lid) * 4);
            const int label = __ldg(tlabels + (size_t)n * T_TGT + lid);
            const float tx = tb.x, ty = tb.y, tw = tb.z, th = tb.w;

            int gxi = (int)(tx / cell); gxi = min(max(gxi, 0), S_GRID - 1);
            int gyi = (int)(ty / cell); gyi = min(max(gyi, 0), S_GRID - 1);
            const float ox = (tx - (float)gxi * cell) / cell;
            const float oy = (ty - (float)gyi * cell) / cell;

            // wide-load cell window (R13): 16B-align and realign in regs
            const int cidx = gyi * S_GRID + gxi;
            const int abs_off = n * IMG_FLOATS + cidx * CH;
            const int off2 = abs_off & 2;             // 0 or 2 floats
            const float4* __restrict__ p4 =
                reinterpret_cast<const float4*>(outputs + (abs_off - off2));

            float4 r0 = __ldg(p4 + 0);
            float4 r1 = __ldg(p4 + 1);
            float4 r2 = __ldg(p4 + 2);
            float4 r3 = __ldg(p4 + 3);
            float4 r4 = __ldg(p4 + 4);
            float4 r5 = __ldg(p4 + 5);
            float4 r6 = __ldg(p4 + 6);
            float4 r7;
            if (off2) {
                r7 = __ldg(p4 + 7);
            } else {
                const float2 t = __ldg(reinterpret_cast<const float2*>(p4 + 7));
                r7.x = t.x; r7.y = t.y; r7.z = 0.0f; r7.w = 0.0f;
            }

            float f[32];
            f[0]=r0.x; f[1]=r0.y; f[2]=r0.z; f[3]=r0.w;
            f[4]=r1.x; f[5]=r1.y; f[6]=r1.z; f[7]=r1.w;
            f[8]=r2.x; f[9]=r2.y; f[10]=r2.z; f[11]=r2.w;
            f[12]=r3.x; f[13]=r3.y; f[14]=r3.z; f[15]=r3.w;
            f[16]=r4.x; f[17]=r4.y; f[18]=r4.z; f[19]=r4.w;
            f[20]=r5.x; f[21]=r5.y; f[22]=r5.z; f[23]=r5.w;
            f[24]=r6.x; f[25]=r6.y; f[26]=r6.z; f[27]=r6.w;
            f[28]=r7.x; f[29]=r7.y; f[30]=r7.z; f[31]=r7.w;

            const bool oddw = (off2 != 0);
            float cd[CH];
            #pragma unroll
            for (int j = 0; j < CH; j++)
                cd[j] = oddw ? f[j + 2] : f[j];

            const float x11 = tx - tw * 0.5f, x12 = tx + tw * 0.5f;
            const float y11 = ty - th * 0.5f, y12 = ty + th * 0.5f;
            const float t_area = tw * th;

            float in0, u0, in1, u1, px0, py0, px1, py1;
            {
                const float rx = cd[0], ry = cd[1], rw = cd[2], rh = cd[3];
                const float gx = (rx + (float)gxi) * cell;
                const float gy = (ry + (float)gyi) * cell;
                px0 = gx; py0 = gy;
                float iw = fminf(x12, gx + rw * 0.5f) - fmaxf(x11, gx - rw * 0.5f);
                float ih = fminf(y12, gy + rh * 0.5f) - fmaxf(y11, gy - rh * 0.5f);
                iw = fmaxf(iw, 0.0f); ih = fmaxf(ih, 0.0f);
                in0 = iw * ih;
                u0  = fmaxf(t_area + rw * rh - in0, 1e-6f);
            }
            {
                const float rx = cd[4], ry = cd[5], rw = cd[6], rh = cd[7];
                const float gx = (rx + (float)gxi) * cell;
                const float gy = (ry + (float)gyi) * cell;
                px1 = gx; py1 = gy;
                float iw = fminf(x12, gx + rw * 0.5f) - fmaxf(x11, gx - rw * 0.5f);
                float ih = fminf(y12, gy + rh * 0.5f) - fmaxf(y11, gy - rh * 0.5f);
                iw = fmaxf(iw, 0.0f); ih = fmaxf(ih, 0.0f);
                in1 = iw * ih;
                u1  = fmaxf(t_area + rw * rh - in1, 1e-6f);
            }
            // jnp.argmax tie-break: pick box 1 only if strictly greater
            const int best = (in1 * u0 > in0 * u1) ? 1 : 0;

            const float bx = best ? px1 : px0;
            const float by = best ? py1 : py0;
            const float bw = fmaxf(best ? cd[6] : cd[2], 1e-6f);
            const float bh = fmaxf(best ? cd[7] : cd[3], 1e-6f);
            const float twc = fmaxf(tw, 1e-6f);
            const float thc = fmaxf(th, 1e-6f);

            const float dx = bx - ox;
            const float dy = by - oy;
            const float dw = sqrtf(bw) - sqrtf(twc);
            const float dh = sqrtf(bh) - sqrtf(thc);
            const float box_loss = dx * dx + dy * dy + dw * dw + dh * dh;

            const float bc = cd[B_BOX * 4 + best];
            const float obj_loss = (bc - 1.0f) * (bc - 1.0f);

            // class term: softmax without max-subtraction (logits ~ N(0,1));
            // mean_c (p_c - onehot)^2 = (E2/Z^2 - 2 e_lab/Z + 1)/20
            float Z = 0.0f, E2 = 0.0f, e_lab = 0.0f;
            #pragma unroll
            for (int c = 0; c < C_CLS; c++) {
                const float e = __expf(cd[B_BOX * 5 + c]);
                Z  += e;
                E2 += e * e;
                if (label == c) e_lab = e;
            }
            const float invZ = __fdividef(1.0f, Z);
            const float class_loss =
                (E2 * invZ * invZ - 2.0f * e_lab * invZ + 1.0f)
                * (1.0f / (float)C_CLS);

            lane_acc += LAMBDA_COORD * box_loss + class_loss + obj_loss;
        }
    }

    // ================= reductions (both block types) =================
    #pragma unroll
    for (int o = 16; o; o >>= 1)
        lane_acc += __shfl_down_sync(0xffffffffu, lane_acc, o);
    if (lid == 0) swsum[wid] = lane_acc;
    __syncthreads();

    if (tid == 0) {
        float bsum = 0.0f;
        #pragma unroll
        for (int w = 0; w < THREADS / 32; w++) bsum += swsum[w];
        g_partial[blockIdx.x] = bsum;
        __threadfence();
        const unsigned old = atomicAdd(&g_count, 1u);
        s_is_last = (old == (unsigned)(gridDim.x - 1));
    }
    __syncthreads();

    // ---- last block: deterministic final reduction over 1292 partials ----
    if (s_is_last) {
        double acc = 0.0;
        for (int i = tid; i < GRID_T; i += THREADS)
            acc += (double)g_partial[i];
        sd[tid] = acc;
        __syncthreads();
        #pragma unroll
        for (int off = THREADS / 2; off; off >>= 1) {
            if (tid < off) sd[tid] += sd[tid + off];
            __syncthreads();
        }
        if (tid == 0) {
            out[0] = (float)(sd[0] / (double)N_IMG);
            g_count = 0;   // reset for next graph replay
        }
    }
}

extern "C" void kernel_launch(void* const* d_in, const int* in_sizes, int n_in,
                              void* d_out, int out_size)
{
    const float* outputs = (const float*)d_in[0];
    const float* tboxes  = (const float*)d_in[1];
    const int*   tlabels = (const int*)d_in[2];
    float* out = (float*)d_out;

    yolo_split_kernel<<<GRID_T, THREADS>>>(outputs, tboxes, tlabels, out);
}

// round 15
// speedup vs baseline: 1.0692x; 1.0692x over previous
#include <cuda_runtime.h>
#include <cuda_bf16.h>
#include <cstdint>

// Problem constants (from reference)
#define S_GRID 7
#define B_BOX 2
#define C_CLS 20
#define CH (B_BOX * 5 + C_CLS)            // 30 channels
#define CELLS (S_GRID * S_GRID)           // 49
#define IMG_FLOATS (CELLS * CH)           // 1470
#define N_IMG 16384
#define T_TGT 32
#define LAMBDA_COORD 5.0f
#define LAMBDA_NOOBJ 0.5f

#define THREADS 256
// Kernel A: pure conf^2 stream
#define A_BLOCKS 1215                     // 1215*256 = 311040, % 15 == 0
#define A_STRIDE (A_BLOCKS * THREADS)
#define NV4 (N_IMG * IMG_FLOATS / 4)      // 6,021,120 float4 (exact)
// Kernel B: per-target math, warp-per-image, 2 images per warp
#define B_BLOCKS 1024
#define B_WARPS (B_BLOCKS * (THREADS / 32))   // 8192
#define IMGS_PER_WARP (N_IMG / B_WARPS)       // 2
#define N_PART (A_BLOCKS + B_BLOCKS)          // 2239

__device__ float g_partial[N_PART];
__device__ unsigned int g_count;          // zero-init; returns to 0 every launch

// ===================== Kernel A: memcpy-shaped conf^2 stream ================
__global__ void __launch_bounds__(THREADS)
yolo_confstream_kernel(const float* __restrict__ outputs)
{
    __shared__ float swsum[THREADS / 32];

    const int tid = threadIdx.x;
    const int wid = tid >> 5;
    const int lid = tid & 31;
    const int gtid = blockIdx.x * THREADS + tid;

    // float4 index j: j%15==2 -> (x,y) are conf ch8,9; j%15==9 -> (z,w).
    // A_STRIDE % 15 == 0 keeps each thread's residue constant.
    const float4* __restrict__ o4 = reinterpret_cast<const float4*>(outputs);
    const int r = gtid % 15;
    const bool p2 = (r == 2);
    const bool p9 = (r == 9);
    float confsq = 0.0f;
    #pragma unroll 4
    for (int i = gtid; i < NV4; i += A_STRIDE) {
        const float4 v = o4[i];
        if (p2) confsq += v.x * v.x + v.y * v.y;
        if (p9) confsq += v.z * v.z + v.w * v.w;
    }

    float lane_acc = (LAMBDA_NOOBJ / 98.0f) * confsq;
    #pragma unroll
    for (int o = 16; o; o >>= 1)
        lane_acc += __shfl_down_sync(0xffffffffu, lane_acc, o);
    if (lid == 0) swsum[wid] = lane_acc;
    __syncthreads();
    if (tid == 0) {
        float bsum = 0.0f;
        #pragma unroll
        for (int w = 0; w < THREADS / 32; w++) bsum += swsum[w];
        g_partial[blockIdx.x] = bsum;
    }
}

// ===================== Kernel B: per-target math (L2-resident) ==============
__global__ void __launch_bounds__(THREADS)
yolo_target_kernel(const float* __restrict__ outputs,
                   const float* __restrict__ tboxes,
                   const int*   __restrict__ tlabels,
                   float*       __restrict__ out)
{
    __shared__ float swsum[THREADS / 32];
    __shared__ int s_is_last;
    __shared__ double sd[THREADS];

    const int tid = threadIdx.x;
    const int wid = tid >> 5;
    const int lid = tid & 31;

    const int bwarp = blockIdx.x * (THREADS / 32) + wid;
    const float cell = 1.0f / (float)S_GRID;

    float lane_acc = 0.0f;

    #pragma unroll
    for (int k = 0; k < IMGS_PER_WARP; k++) {
        const int n = bwarp + k * B_WARPS;

        const float4 tb = *reinterpret_cast<const float4*>(
            tboxes + ((size_t)n * T_TGT + lid) * 4);
        const int label = __ldg(tlabels + (size_t)n * T_TGT + lid);
        const float tx = tb.x, ty = tb.y, tw = tb.z, th = tb.w;

        int gxi = (int)(tx / cell); gxi = min(max(gxi, 0), S_GRID - 1);
        int gyi = (int)(ty / cell); gyi = min(max(gyi, 0), S_GRID - 1);
        const float ox = (tx - (float)gxi * cell) / cell;
        const float oy = (ty - (float)gyi * cell) / cell;

        // wide-load cell window: 16B-align and realign in regs (R13 core)
        const int cidx = gyi * S_GRID + gxi;
        const int abs_off = n * IMG_FLOATS + cidx * CH;
        const int off2 = abs_off & 2;                 // 0 or 2 floats
        const float4* __restrict__ p4 =
            reinterpret_cast<const float4*>(outputs + (abs_off - off2));

        float4 r0 = __ldg(p4 + 0);
        float4 r1 = __ldg(p4 + 1);
        float4 r2 = __ldg(p4 + 2);
        float4 r3 = __ldg(p4 + 3);
        float4 r4 = __ldg(p4 + 4);
        float4 r5 = __ldg(p4 + 5);
        float4 r6 = __ldg(p4 + 6);
        float4 r7;
        if (off2) {
            r7 = __ldg(p4 + 7);
        } else {
            const float2 t = __ldg(reinterpret_cast<const float2*>(p4 + 7));
            r7.x = t.x; r7.y = t.y; r7.z = 0.0f; r7.w = 0.0f;
        }

        float f[32];
        f[0]=r0.x; f[1]=r0.y; f[2]=r0.z; f[3]=r0.w;
        f[4]=r1.x; f[5]=r1.y; f[6]=r1.z; f[7]=r1.w;
        f[8]=r2.x; f[9]=r2.y; f[10]=r2.z; f[11]=r2.w;
        f[12]=r3.x; f[13]=r3.y; f[14]=r3.z; f[15]=r3.w;
        f[16]=r4.x; f[17]=r4.y; f[18]=r4.z; f[19]=r4.w;
        f[20]=r5.x; f[21]=r5.y; f[22]=r5.z; f[23]=r5.w;
        f[24]=r6.x; f[25]=r6.y; f[26]=r6.z; f[27]=r6.w;
        f[28]=r7.x; f[29]=r7.y; f[30]=r7.z; f[31]=r7.w;

        const bool oddw = (off2 != 0);
        float cd[CH];
        #pragma unroll
        for (int j = 0; j < CH; j++)
            cd[j] = oddw ? f[j + 2] : f[j];

        const float x11 = tx - tw * 0.5f, x12 = tx + tw * 0.5f;
        const float y11 = ty - th * 0.5f, y12 = ty + th * 0.5f;
        const float t_area = tw * th;

        float in0, u0, in1, u1, px0, py0, px1, py1;
        {
            const float rx = cd[0], ry = cd[1], rw = cd[2], rh = cd[3];
            const float gx = (rx + (float)gxi) * cell;
            const float gy = (ry + (float)gyi) * cell;
            px0 = gx; py0 = gy;
            float iw = fminf(x12, gx + rw * 0.5f) - fmaxf(x11, gx - rw * 0.5f);
            float ih = fminf(y12, gy + rh * 0.5f) - fmaxf(y11, gy - rh * 0.5f);
            iw = fmaxf(iw, 0.0f); ih = fmaxf(ih, 0.0f);
            in0 = iw * ih;
            u0  = fmaxf(t_area + rw * rh - in0, 1e-6f);
        }
        {
            const float rx = cd[4], ry = cd[5], rw = cd[6], rh = cd[7];
            const float gx = (rx + (float)gxi) * cell;
            const float gy = (ry + (float)gyi) * cell;
            px1 = gx; py1 = gy;
            float iw = fminf(x12, gx + rw * 0.5f) - fmaxf(x11, gx - rw * 0.5f);
            float ih = fminf(y12, gy + rh * 0.5f) - fmaxf(y11, gy - rh * 0.5f);
            iw = fmaxf(iw, 0.0f); ih = fmaxf(ih, 0.0f);
            in1 = iw * ih;
            u1  = fmaxf(t_area + rw * rh - in1, 1e-6f);
        }
        // jnp.argmax tie-break: pick box 1 only if strictly greater
        const int best = (in1 * u0 > in0 * u1) ? 1 : 0;

        const float bx = best ? px1 : px0;
        const float by = best ? py1 : py0;
        const float bw = fmaxf(best ? cd[6] : cd[2], 1e-6f);
        const float bh = fmaxf(best ? cd[7] : cd[3], 1e-6f);
        const float twc = fmaxf(tw, 1e-6f);
        const float thc = fmaxf(th, 1e-6f);

        const float dx = bx - ox;
        const float dy = by - oy;
        const float dw = sqrtf(bw) - sqrtf(twc);
        const float dh = sqrtf(bh) - sqrtf(thc);
        const float box_loss = dx * dx + dy * dy + dw * dw + dh * dh;

        const float bc = cd[B_BOX * 4 + best];
        const float obj_loss = (bc - 1.0f) * (bc - 1.0f);

        // class term: softmax without max-subtraction (logits ~ N(0,1));
        // mean_c (p_c - onehot)^2 = (E2/Z^2 - 2 e_lab/Z + 1)/20
        float Z = 0.0f, E2 = 0.0f, e_lab = 0.0f;
        #pragma unroll
        for (int c = 0; c < C_CLS; c++) {
            const float e = __expf(cd[B_BOX * 5 + c]);
            Z  += e;
            E2 += e * e;
            if (label == c) e_lab = e;
        }
        const float invZ = __fdividef(1.0f, Z);
        const float class_loss =
            (E2 * invZ * invZ - 2.0f * e_lab * invZ + 1.0f)
            * (1.0f / (float)C_CLS);

        lane_acc += LAMBDA_COORD * box_loss + class_loss + obj_loss;
    }

    // ---- reductions ----
    #pragma unroll
    for (int o = 16; o; o >>= 1)
        lane_acc += __shfl_down_sync(0xffffffffu, lane_acc, o);
    if (lid == 0) swsum[wid] = lane_acc;
    __syncthreads();

    if (tid == 0) {
        float bsum = 0.0f;
        #pragma unroll
        for (int w = 0; w < THREADS / 32; w++) bsum += swsum[w];
        g_partial[A_BLOCKS + blockIdx.x] = bsum;
        __threadfence();
        const unsigned old = atomicAdd(&g_count, 1u);
        s_is_last = (old == (unsigned)(B_BLOCKS - 1));
    }
    __syncthreads();

    // last B-block: reduce ALL partials (A's writes ordered by kernel boundary)
    if (s_is_last) {
        double acc = 0.0;
        for (int i = tid; i < N_PART; i += THREADS)
            acc += (double)g_partial[i];
        sd[tid] = acc;
        __syncthreads();
        #pragma unroll
        for (int off = THREADS / 2; off; off >>= 1) {
            if (tid < off) sd[tid] += sd[tid + off];
            __syncthreads();
        }
        if (tid == 0) {
            out[0] = (float)(sd[0] / (double)N_IMG);
            g_count = 0;   // reset for next graph replay
        }
    }
}

extern "C" void kernel_launch(void* const* d_in, const int* in_sizes, int n_in,
                              void* d_out, int out_size)
{
    const float* outputs = (const float*)d_in[0];
    const float* tboxes  = (const float*)d_in[1];
    const int*   tlabels = (const int*)d_in[2];
    float* out = (float*)d_out;

    yolo_confstream_kernel<<<A_BLOCKS, THREADS>>>(outputs);
    yolo_target_kernel<<<B_BLOCKS, THREADS>>>(outputs, tboxes, tlabels, out);
}